// round 16
// baseline (speedup 1.0000x reference)
#include <cuda_runtime.h>

#define NPTS    2048
#define NPAIR   (NPTS/2)             // 1024 point-pairs
#define UPR     10
#define NJIT    (NPTS*UPR)           // 20480
#define QTOT    (NJIT + NPTS)        // 22528
#define KNN     5
#define TA      512                  // kernel A: 16 warps = 16 scan segments
#define NSEG    16
#define SPAIRS  (NPAIR/NSEG)         // 64 pairs per segment
#define NOCT    8                    // collection octants (pass 2)
#define OPAIRS  (NPAIR/NOCT)         // 128 pairs per octant
#define GA      256                  // 4 categories x 64 groups
#define SEGCAP  32
#define NCAND   (NOCT*SEGCAP)        // 256 candidate slots per (cloud,parent)
#define TB      128
#define GB      ((2*QTOT)/TB)        // 352
#define EPS_D   1e-8f
#define EPS_N   1e-10f
#define BETA    3.0f
#define STDV    0.05f
#define IDXMASK 0xFFFFF800u

__device__ float4   g_srcgrad[2][NPTS];        // src-query grads
__device__ float4   g_cand[2][NPTS][NCAND];    // candidate coords {x,y,z,|p|^2}
__device__ int      g_cnt[2][NPTS][NOCT];      // per-octant candidate counts
__device__ float    g_d5[2][NPTS];             // exact parent 5NN distance
__device__ float    g_partial[GB];
__device__ unsigned g_ticket;

__device__ __forceinline__ void ins5key(int key, int& s0, int& s1, int& s2, int& s3, int& s4) {
    s4 = key;
    int a;
    a = min(s3, s4); s4 = max(s3, s4); s3 = a;
    a = min(s2, s3); s3 = max(s2, s3); s2 = a;
    a = min(s1, s2); s2 = max(s1, s2); s1 = a;
    a = min(s0, s1); s1 = max(s0, s1); s0 = a;
}

__device__ __forceinline__ unsigned long long packf2(float lo, float hi) {
    unsigned long long r;
    asm("mov.b64 %0, {%1, %2};" : "=l"(r) : "f"(lo), "f"(hi));
    return r;
}

// ================= Kernel A: full scans (parents + src queries) =============
__global__ __launch_bounds__(TA)
void kernelA(const float* __restrict__ src,
             const float* __restrict__ tgt,
             const float* __restrict__ noise)
{
    __shared__ float4 sC[NPTS];               // 32 KB pair-SoA cloud
    __shared__ int    sKeys[NSEG-1][KNN][32]; // 9.4 KB merge buffer
    __shared__ float  sR2[32];                // per-task collection radius^2

    const int tid  = threadIdx.x;
    const int lane = tid & 31;
    const int seg  = tid >> 5;                // 0..15 scan segment
    const int b    = blockIdx.x;
    const int cat  = b >> 6;                  // 0: tgtP/tgt 1: tgtP/src 2: srcQ/tgt 3: srcQ/src
    const int grp  = b & 63;
    const bool isParent = (cat < 2);
    const float* __restrict__ cld = (cat & 1) ? src : tgt;

    for (int i = tid; i < NPTS; i += TA) {
        float x = cld[3*i], y = cld[3*i+1], z = cld[3*i+2];
        float w = fmaf(x, x, fmaf(y, y, z * z));
        int pj = i >> 1, h = i & 1;
        float* base = (float*)&sC[2 * pj];
        base[0 + h] = x; base[2 + h] = y; base[4 + h] = z; base[6 + h] = w;
    }
    __syncthreads();

    const int task = grp * 32 + lane;         // 0..2047
    const float* __restrict__ qp = isParent ? tgt : src;
    const float qx = qp[3*task], qy = qp[3*task+1], qz = qp[3*task+2];
    const float qx2 = -2.0f * qx, qy2 = -2.0f * qy, qz2 = -2.0f * qz;
    const float q2  = fmaf(qx, qx, fmaf(qy, qy, qz * qz));
    const unsigned long long qxp = packf2(qx2, qx2);
    const unsigned long long qyp = packf2(qy2, qy2);
    const unsigned long long qzp = packf2(qz2, qz2);

    int s0 = 0x7F000000, s1 = 0x7F000001, s2 = 0x7F000002,
        s3 = 0x7F000003, s4 = 0x7F000004;
    float thr = __int_as_float(s4) - q2;

    // Pass 1: broadcast scan of this warp's segment (uniform addr, no conflicts).
    const ulonglong2* pc = reinterpret_cast<const ulonglong2*>(sC) + seg * (SPAIRS * 2);
    const int joff = seg * (SPAIRS * 2);      // point-index offset

    if (isParent) {
        // value-only inserts (no index packing; clamp keeps float-bit ordering)
#pragma unroll 4
        for (int k = 0; k < SPAIRS / 2; ++k) {
            ulonglong2 A0 = pc[4 * k];
            ulonglong2 B0 = pc[4 * k + 1];
            ulonglong2 A1 = pc[4 * k + 2];
            ulonglong2 B1 = pc[4 * k + 3];
            unsigned long long ra, rb;
            asm("fma.rn.f32x2 %0, %1, %2, %3;" : "=l"(ra) : "l"(B0.x), "l"(qzp), "l"(B0.y));
            asm("fma.rn.f32x2 %0, %1, %2, %3;" : "=l"(rb) : "l"(B1.x), "l"(qzp), "l"(B1.y));
            asm("fma.rn.f32x2 %0, %1, %2, %3;" : "=l"(ra) : "l"(A0.y), "l"(qyp), "l"(ra));
            asm("fma.rn.f32x2 %0, %1, %2, %3;" : "=l"(rb) : "l"(A1.y), "l"(qyp), "l"(rb));
            asm("fma.rn.f32x2 %0, %1, %2, %3;" : "=l"(ra) : "l"(A0.x), "l"(qxp), "l"(ra));
            asm("fma.rn.f32x2 %0, %1, %2, %3;" : "=l"(rb) : "l"(A1.x), "l"(qxp), "l"(rb));
            float r0, r1, r2, r3;
            asm("mov.b64 {%0, %1}, %2;" : "=f"(r0), "=f"(r1) : "l"(ra));
            asm("mov.b64 {%0, %1}, %2;" : "=f"(r2), "=f"(r3) : "l"(rb));

            if (fminf(fminf(r0, r1), fminf(r2, r3)) < thr) {
                if (r0 < thr) {
                    ins5key(__float_as_int(fmaxf(r0 + q2, 0.0f)), s0, s1, s2, s3, s4);
                    thr = __int_as_float(s4) - q2;
                }
                if (r1 < thr) {
                    ins5key(__float_as_int(fmaxf(r1 + q2, 0.0f)), s0, s1, s2, s3, s4);
                    thr = __int_as_float(s4) - q2;
                }
                if (r2 < thr) {
                    ins5key(__float_as_int(fmaxf(r2 + q2, 0.0f)), s0, s1, s2, s3, s4);
                    thr = __int_as_float(s4) - q2;
                }
                if (r3 < thr) {
                    ins5key(__float_as_int(fmaxf(r3 + q2, 0.0f)), s0, s1, s2, s3, s4);
                    thr = __int_as_float(s4) - q2;
                }
            }
        }
    } else {
        // keyed inserts (indices needed for exact epilogue)
#pragma unroll 4
        for (int k = 0; k < SPAIRS / 2; ++k) {
            ulonglong2 A0 = pc[4 * k];
            ulonglong2 B0 = pc[4 * k + 1];
            ulonglong2 A1 = pc[4 * k + 2];
            ulonglong2 B1 = pc[4 * k + 3];
            unsigned long long ra, rb;
            asm("fma.rn.f32x2 %0, %1, %2, %3;" : "=l"(ra) : "l"(B0.x), "l"(qzp), "l"(B0.y));
            asm("fma.rn.f32x2 %0, %1, %2, %3;" : "=l"(rb) : "l"(B1.x), "l"(qzp), "l"(B1.y));
            asm("fma.rn.f32x2 %0, %1, %2, %3;" : "=l"(ra) : "l"(A0.y), "l"(qyp), "l"(ra));
            asm("fma.rn.f32x2 %0, %1, %2, %3;" : "=l"(rb) : "l"(A1.y), "l"(qyp), "l"(rb));
            asm("fma.rn.f32x2 %0, %1, %2, %3;" : "=l"(ra) : "l"(A0.x), "l"(qxp), "l"(ra));
            asm("fma.rn.f32x2 %0, %1, %2, %3;" : "=l"(rb) : "l"(A1.x), "l"(qxp), "l"(rb));
            float r0, r1, r2, r3;
            asm("mov.b64 {%0, %1}, %2;" : "=f"(r0), "=f"(r1) : "l"(ra));
            asm("mov.b64 {%0, %1}, %2;" : "=f"(r2), "=f"(r3) : "l"(rb));

            if (fminf(fminf(r0, r1), fminf(r2, r3)) < thr) {
                int jbase = joff + (k << 2);
                if (r0 < thr) {
                    float d2 = r0 + q2;
                    ins5key((int)((__float_as_uint(d2) & IDXMASK) | (unsigned)jbase), s0, s1, s2, s3, s4);
                    thr = __int_as_float(s4) - q2;
                }
                if (r1 < thr) {
                    float d2 = r1 + q2;
                    ins5key((int)((__float_as_uint(d2) & IDXMASK) | (unsigned)(jbase + 1)), s0, s1, s2, s3, s4);
                    thr = __int_as_float(s4) - q2;
                }
                if (r2 < thr) {
                    float d2 = r2 + q2;
                    ins5key((int)((__float_as_uint(d2) & IDXMASK) | (unsigned)(jbase + 2)), s0, s1, s2, s3, s4);
                    thr = __int_as_float(s4) - q2;
                }
                if (r3 < thr) {
                    float d2 = r3 + q2;
                    ins5key((int)((__float_as_uint(d2) & IDXMASK) | (unsigned)(jbase + 3)), s0, s1, s2, s3, s4);
                    thr = __int_as_float(s4) - q2;
                }
            }
        }
    }

    if (seg) {
        sKeys[seg - 1][0][lane] = s0;
        sKeys[seg - 1][1][lane] = s1;
        sKeys[seg - 1][2][lane] = s2;
        sKeys[seg - 1][3][lane] = s3;
        sKeys[seg - 1][4][lane] = s4;
    }
    __syncthreads();

    if (seg == 0) {
#pragma unroll
        for (int w = 0; w < NSEG - 1; ++w) {
#pragma unroll
            for (int r = 0; r < KNN; ++r) {
                int o = sKeys[w][r][lane];
                if (o < s4) ins5key(o, s0, s1, s2, s3, s4);
            }
        }
        if (isParent) {
            float dl2 = 0.f;
#pragma unroll
            for (int u = 0; u < UPR; ++u) {
                int nb = 3 * (task * UPR + u);
                float nx = noise[nb], ny = noise[nb+1], nz = noise[nb+2];
                dl2 = fmaxf(dl2, fmaf(nx, nx, fmaf(ny, ny, nz * nz)));
            }
            float dl = STDV * sqrtf(dl2);
            float d5 = sqrtf(__int_as_float(s4));   // exact, non-negative by clamp
            float R  = fmaf(d5, 1.002f, 2.0f * dl + 1e-4f);
            sR2[lane] = R * R;
            g_d5[cat][task] = d5;
        } else {
            float aw = 0.f, gx = 0.f, gy = 0.f, gz = 0.f;
            int keys[KNN] = {s0, s1, s2, s3, s4};
#pragma unroll
            for (int kk = 0; kk < KNN; ++kk) {
                int idx = keys[kk] & 2047;
                int pj = idx >> 1, h = idx & 1;
                const float* base = (const float*)&sC[2 * pj];
                float dx = qx - base[0 + h], dy = qy - base[2 + h], dz = qz - base[4 + h];
                float d2 = fmaf(dx, dx, fmaf(dy, dy, dz * dz));
                float w  = 1.0f / (d2 + EPS_D);
                aw += w;
                gx = fmaf(dx, w, gx);
                gy = fmaf(dy, w, gy);
                gz = fmaf(dz, w, gz);
            }
            float inv = 1.0f / aw;
            g_srcgrad[cat - 2][task] = make_float4(gx * inv, gy * inv, gz * inv, 0.f);
        }
    }
    __syncthreads();

    if (isParent && seg < NOCT) {
        const int oct = seg;
        const float thrC = sR2[lane] - q2;
        int c = 0;
        float4* out = &g_cand[cat][task][oct * SEGCAP];
#pragma unroll 2
        for (int k = 0; k < OPAIRS; ++k) {
            int pj = oct * OPAIRS + k;
            float4 a  = sC[2 * pj];
            float4 bb = sC[2 * pj + 1];
            float r0 = fmaf(a.x, qx2, fmaf(a.z, qy2, fmaf(bb.x, qz2, bb.z)));
            float r1 = fmaf(a.y, qx2, fmaf(a.w, qy2, fmaf(bb.y, qz2, bb.w)));
            if (r0 <= thrC) { if (c < SEGCAP) out[c] = make_float4(a.x, a.z, bb.x, bb.z); c++; }
            if (r1 <= thrC) { if (c < SEGCAP) out[c] = make_float4(a.y, a.w, bb.y, bb.w); c++; }
        }
        g_cnt[cat][task][oct] = c;   // c > SEGCAP signals overflow
    }
}

// ================= Kernel B: jitter queries + combine + fused reduce ========
__global__ __launch_bounds__(TB)
void kernelB(const float* __restrict__ src,
             const float* __restrict__ tgt,
             const float* __restrict__ noise)
{
    __shared__ float sh[TB / 32];
    __shared__ bool  isLast;
    const int tid  = threadIdx.x;
    const int gidx = blockIdx.x * TB + tid;
    const int qv   = gidx >> 1;
    const int cat  = gidx & 1;       // 0 = vs tgt, 1 = vs src

    float4 g;
    if (qv < NJIT) {
        const int m = qv / UPR;
        float nx = noise[3*qv + 0], ny = noise[3*qv + 1], nz = noise[3*qv + 2];
        float qx = fmaf(nx, STDV, tgt[3*m + 0]);
        float qy = fmaf(ny, STDV, tgt[3*m + 1]);
        float qz = fmaf(nz, STDV, tgt[3*m + 2]);
        const float qx2 = -2.0f * qx, qy2 = -2.0f * qy, qz2 = -2.0f * qz;
        const float q2  = fmaf(qx, qx, fmaf(qy, qy, qz * qz));

        // Warm sentinel threshold: (d5_parent + |jitter|)^2, inflated.
        float dq  = STDV * sqrtf(fmaf(nx, nx, fmaf(ny, ny, nz * nz)));
        float bnd = g_d5[cat][m] + dq;
        float sv  = fmaf(bnd, bnd, 1e-7f) * 1.001f;
        int sent  = (int)((__float_as_uint(sv) & IDXMASK) | 0x7FFu);

        int s0 = sent, s1 = sent, s2 = sent, s3 = sent, s4 = sent;
        float thrD = __int_as_float(sent);

        const float4* __restrict__ cl = g_cand[cat][m];
        const int4* cn4 = reinterpret_cast<const int4*>(g_cnt[cat][m]);
        int4 cA = cn4[0], cB = cn4[1];
        int cnts[NOCT] = {cA.x, cA.y, cA.z, cA.w, cB.x, cB.y, cB.z, cB.w};
        bool ovf = false;
#pragma unroll
        for (int sgi = 0; sgi < NOCT; ++sgi) ovf |= (cnts[sgi] > SEGCAP);

        if (!ovf) {
#pragma unroll
            for (int sgi = 0; sgi < NOCT; ++sgi) {
                int n = cnts[sgi];
                const float4* p = cl + sgi * SEGCAP;
                for (int i = 0; i < n; ++i) {
                    float4 c = p[i];
                    float r  = fmaf(c.x, qx2, fmaf(c.y, qy2, fmaf(c.z, qz2, c.w)));
                    float d2 = r + q2;
                    if (d2 < thrD) {
                        ins5key((int)((__float_as_uint(d2) & IDXMASK) | (unsigned)(sgi * SEGCAP + i)),
                                s0, s1, s2, s3, s4);
                        thrD = __int_as_float(s4);
                    }
                }
            }
            float aw = 0.f, gx = 0.f, gy = 0.f, gz = 0.f;
            int keys[KNN] = {s0, s1, s2, s3, s4};
#pragma unroll
            for (int kk = 0; kk < KNN; ++kk) {
                int ci = min(keys[kk] & 2047, NCAND - 1);   // defensive clamp
                float4 c = cl[ci];
                float dx = qx - c.x, dy = qy - c.y, dz = qz - c.z;
                float d2 = fmaf(dx, dx, fmaf(dy, dy, dz * dz));
                float w  = 1.0f / (d2 + EPS_D);
                aw += w;
                gx = fmaf(dx, w, gx);
                gy = fmaf(dy, w, gy);
                gz = fmaf(dz, w, gz);
            }
            float inv = 1.0f / aw;
            g = make_float4(gx * inv, gy * inv, gz * inv, 0.f);
        } else {
            // overflow fallback: exact full scan from global (rare)
            const float* fp = cat ? src : tgt;
            s0 = 0x7F000000; s1 = 0x7F000001; s2 = 0x7F000002;
            s3 = 0x7F000003; s4 = 0x7F000004;
            thrD = __int_as_float(s4);
            for (int idx = 0; idx < NPTS; ++idx) {
                float x = fp[3*idx], y = fp[3*idx+1], z = fp[3*idx+2];
                float w = fmaf(x, x, fmaf(y, y, z * z));
                float r = fmaf(x, qx2, fmaf(y, qy2, fmaf(z, qz2, w)));
                float d2 = r + q2;
                if (d2 < thrD) {
                    ins5key((int)((__float_as_uint(d2) & IDXMASK) | (unsigned)idx),
                            s0, s1, s2, s3, s4);
                    thrD = __int_as_float(s4);
                }
            }
            float aw = 0.f, gx = 0.f, gy = 0.f, gz = 0.f;
            int keys[KNN] = {s0, s1, s2, s3, s4};
#pragma unroll
            for (int kk = 0; kk < KNN; ++kk) {
                int idx = keys[kk] & 2047;
                float dx = qx - fp[3*idx], dy = qy - fp[3*idx+1], dz = qz - fp[3*idx+2];
                float d2 = fmaf(dx, dx, fmaf(dy, dy, dz * dz));
                float w  = 1.0f / (d2 + EPS_D);
                aw += w;
                gx = fmaf(dx, w, gx);
                gy = fmaf(dy, w, gy);
                gz = fmaf(dz, w, gz);
            }
            float inv = 1.0f / aw;
            g = make_float4(gx * inv, gy * inv, gz * inv, 0.f);
        }
    } else {
        g = g_srcgrad[cat][qv - NJIT];
    }

    // partner-lane combine: cat0 holds gT, receives gS from cat1 lane.
    float ox = __shfl_xor_sync(0xFFFFFFFFu, g.x, 1);
    float oy = __shfl_xor_sync(0xFFFFFFFFu, g.y, 1);
    float oz = __shfl_xor_sync(0xFFFFFFFFu, g.z, 1);

    float v = 0.f;
    if (cat == 0) {
        float axT = g.x + EPS_N, ayT = g.y + EPS_N, azT = g.z + EPS_N;
        float axS = ox  + EPS_N, ayS = oy  + EPS_N, azS = oz  + EPS_N;
        float uT = sqrtf(fmaf(axT, axT, fmaf(ayT, ayT, azT * azT)));
        float uS = sqrtf(fmaf(axS, axS, fmaf(ayS, ayS, azS * azS)));
        float e1 = fabsf(uT - uS);
        float e2 = fabsf(ox - g.x) + fabsf(oy - g.y) + fabsf(oz - g.z);
        float tt = e1 + e2;
        v = tt * __expf(-BETA * tt);
    }

#pragma unroll
    for (int o = 16; o > 0; o >>= 1) v += __shfl_down_sync(0xFFFFFFFFu, v, o);
    if ((tid & 31) == 0) sh[tid >> 5] = v;
    __syncthreads();
    if (tid == 0) {
        float s = 0.f;
#pragma unroll
        for (int w = 0; w < TB / 32; ++w) s += sh[w];
        g_partial[blockIdx.x] = s;
        __threadfence();
        unsigned t = atomicAdd(&g_ticket, 1u);
        isLast = (t == GB - 1);
    }
    __syncthreads();

    // Last block performs the deterministic final reduction.
    if (isLast && tid < 32) {
        __threadfence();
        float acc = 0.f;
        for (int i = tid; i < GB; i += 32) acc += g_partial[i];
#pragma unroll
        for (int o = 16; o > 0; o >>= 1) acc += __shfl_down_sync(0xFFFFFFFFu, acc, o);
        if (tid == 0) {
            ((float*)0)[0];   // placeholder removed — see note below
        }
    }
}

// NOTE: output pointer must reach kernelB — wrapper passes it as a parameter.
// (The placeholder above is never compiled; real definition follows.)

__global__ void final_dummy() {}

extern "C" void kernel_launch(void* const* d_in, const int* in_sizes, int n_in,
                              void* d_out, int out_size);

// Redefine kernelB properly with out pointer via a thin wrapper kernel is
// avoided; instead we pass d_out directly:
__global__ __launch_bounds__(TB)
void kernelB_out(const float* __restrict__ src,
                 const float* __restrict__ tgt,
                 const float* __restrict__ noise,
                 float* __restrict__ out);

extern "C" void kernel_launch(void* const* d_in, const int* in_sizes, int n_in,
                              void* d_out, int out_size)
{
    const float* src   = (const float*)d_in[0];
    const float* tgt   = (const float*)d_in[1];
    const float* noise = (const float*)d_in[2];
    (void)in_sizes; (void)n_in; (void)out_size;

    kernelA<<<GA, TA>>>(src, tgt, noise);
    kernelB_out<<<GB, TB>>>(src, tgt, noise, (float*)d_out);
}

// Full kernelB with output pointer (identical body; writes out[0] and resets ticket).
__global__ __launch_bounds__(TB)
void kernelB_out(const float* __restrict__ src,
                 const float* __restrict__ tgt,
                 const float* __restrict__ noise,
                 float* __restrict__ out)
{
    __shared__ float sh[TB / 32];
    __shared__ bool  isLast;
    const int tid  = threadIdx.x;
    const int gidx = blockIdx.x * TB + tid;
    const int qv   = gidx >> 1;
    const int cat  = gidx & 1;

    float4 g;
    if (qv < NJIT) {
        const int m = qv / UPR;
        float nx = noise[3*qv + 0], ny = noise[3*qv + 1], nz = noise[3*qv + 2];
        float qx = fmaf(nx, STDV, tgt[3*m + 0]);
        float qy = fmaf(ny, STDV, tgt[3*m + 1]);
        float qz = fmaf(nz, STDV, tgt[3*m + 2]);
        const float qx2 = -2.0f * qx, qy2 = -2.0f * qy, qz2 = -2.0f * qz;
        const float q2  = fmaf(qx, qx, fmaf(qy, qy, qz * qz));

        float dq  = STDV * sqrtf(fmaf(nx, nx, fmaf(ny, ny, nz * nz)));
        float bnd = g_d5[cat][m] + dq;
        float sv  = fmaf(bnd, bnd, 1e-7f) * 1.001f;
        int sent  = (int)((__float_as_uint(sv) & IDXMASK) | 0x7FFu);

        int s0 = sent, s1 = sent, s2 = sent, s3 = sent, s4 = sent;
        float thrD = __int_as_float(sent);

        const float4* __restrict__ cl = g_cand[cat][m];
        const int4* cn4 = reinterpret_cast<const int4*>(g_cnt[cat][m]);
        int4 cA = cn4[0], cB = cn4[1];
        int cnts[NOCT] = {cA.x, cA.y, cA.z, cA.w, cB.x, cB.y, cB.z, cB.w};
        bool ovf = false;
#pragma unroll
        for (int sgi = 0; sgi < NOCT; ++sgi) ovf |= (cnts[sgi] > SEGCAP);

        if (!ovf) {
#pragma unroll
            for (int sgi = 0; sgi < NOCT; ++sgi) {
                int n = cnts[sgi];
                const float4* p = cl + sgi * SEGCAP;
                for (int i = 0; i < n; ++i) {
                    float4 c = p[i];
                    float r  = fmaf(c.x, qx2, fmaf(c.y, qy2, fmaf(c.z, qz2, c.w)));
                    float d2 = r + q2;
                    if (d2 < thrD) {
                        ins5key((int)((__float_as_uint(d2) & IDXMASK) | (unsigned)(sgi * SEGCAP + i)),
                                s0, s1, s2, s3, s4);
                        thrD = __int_as_float(s4);
                    }
                }
            }
            float aw = 0.f, gx = 0.f, gy = 0.f, gz = 0.f;
            int keys[KNN] = {s0, s1, s2, s3, s4};
#pragma unroll
            for (int kk = 0; kk < KNN; ++kk) {
                int ci = min(keys[kk] & 2047, NCAND - 1);
                float4 c = cl[ci];
                float dx = qx - c.x, dy = qy - c.y, dz = qz - c.z;
                float d2 = fmaf(dx, dx, fmaf(dy, dy, dz * dz));
                float w  = 1.0f / (d2 + EPS_D);
                aw += w;
                gx = fmaf(dx, w, gx);
                gy = fmaf(dy, w, gy);
                gz = fmaf(dz, w, gz);
            }
            float inv = 1.0f / aw;
            g = make_float4(gx * inv, gy * inv, gz * inv, 0.f);
        } else {
            const float* fp = cat ? src : tgt;
            s0 = 0x7F000000; s1 = 0x7F000001; s2 = 0x7F000002;
            s3 = 0x7F000003; s4 = 0x7F000004;
            thrD = __int_as_float(s4);
            for (int idx = 0; idx < NPTS; ++idx) {
                float x = fp[3*idx], y = fp[3*idx+1], z = fp[3*idx+2];
                float w = fmaf(x, x, fmaf(y, y, z * z));
                float r = fmaf(x, qx2, fmaf(y, qy2, fmaf(z, qz2, w)));
                float d2 = r + q2;
                if (d2 < thrD) {
                    ins5key((int)((__float_as_uint(d2) & IDXMASK) | (unsigned)idx),
                            s0, s1, s2, s3, s4);
                    thrD = __int_as_float(s4);
                }
            }
            float aw = 0.f, gx = 0.f, gy = 0.f, gz = 0.f;
            int keys[KNN] = {s0, s1, s2, s3, s4};
#pragma unroll
            for (int kk = 0; kk < KNN; ++kk) {
                int idx = keys[kk] & 2047;
                float dx = qx - fp[3*idx], dy = qy - fp[3*idx+1], dz = qz - fp[3*idx+2];
                float d2 = fmaf(dx, dx, fmaf(dy, dy, dz * dz));
                float w  = 1.0f / (d2 + EPS_D);
                aw += w;
                gx = fmaf(dx, w, gx);
                gy = fmaf(dy, w, gy);
                gz = fmaf(dz, w, gz);
            }
            float inv = 1.0f / aw;
            g = make_float4(gx * inv, gy * inv, gz * inv, 0.f);
        }
    } else {
        g = g_srcgrad[cat][qv - NJIT];
    }

    float ox = __shfl_xor_sync(0xFFFFFFFFu, g.x, 1);
    float oy = __shfl_xor_sync(0xFFFFFFFFu, g.y, 1);
    float oz = __shfl_xor_sync(0xFFFFFFFFu, g.z, 1);

    float v = 0.f;
    if (cat == 0) {
        float axT = g.x + EPS_N, ayT = g.y + EPS_N, azT = g.z + EPS_N;
        float axS = ox  + EPS_N, ayS = oy  + EPS_N, azS = oz  + EPS_N;
        float uT = sqrtf(fmaf(axT, axT, fmaf(ayT, ayT, azT * azT)));
        float uS = sqrtf(fmaf(axS, axS, fmaf(ayS, ayS, azS * azS)));
        float e1 = fabsf(uT - uS);
        float e2 = fabsf(ox - g.x) + fabsf(oy - g.y) + fabsf(oz - g.z);
        float tt = e1 + e2;
        v = tt * __expf(-BETA * tt);
    }

#pragma unroll
    for (int o = 16; o > 0; o >>= 1) v += __shfl_down_sync(0xFFFFFFFFu, v, o);
    if ((tid & 31) == 0) sh[tid >> 5] = v;
    __syncthreads();
    if (tid == 0) {
        float s = 0.f;
#pragma unroll
        for (int w = 0; w < TB / 32; ++w) s += sh[w];
        g_partial[blockIdx.x] = s;
        __threadfence();
        unsigned t = atomicAdd(&g_ticket, 1u);
        isLast = (t == GB - 1);
    }
    __syncthreads();

    if (isLast && tid < 32) {
        __threadfence();
        float acc = 0.f;
        for (int i = tid; i < GB; i += 32) acc += g_partial[i];
#pragma unroll
        for (int o = 16; o > 0; o >>= 1) acc += __shfl_down_sync(0xFFFFFFFFu, acc, o);
        if (tid == 0) {
            out[0] = acc * (1.0f / (float)QTOT);
            g_ticket = 0;   // reset for next graph replay
        }
    }
}

// round 17
// speedup vs baseline: 1.1585x; 1.1585x over previous
#include <cuda_runtime.h>

#define NPTS    2048
#define NPAIR   (NPTS/2)             // 1024 point-pairs
#define UPR     10
#define NJIT    (NPTS*UPR)           // 20480
#define QTOT    (NJIT + NPTS)        // 22528
#define KNN     5
#define TA      512                  // kernel A: 16 warps = 16 scan segments
#define NSEG    16
#define SPAIRS  (NPAIR/NSEG)         // 64 pairs per segment
#define NOCT    8                    // collection octants (pass 2)
#define OPAIRS  (NPAIR/NOCT)         // 128 pairs per octant
#define GA      256                  // 4 categories x 64 groups
#define SEGCAP  32
#define NCAND   (NOCT*SEGCAP)        // 256 candidate slots per (cloud,parent)
#define TB      128
#define GB      ((2*QTOT)/TB)        // 352
#define EPS_D   1e-8f
#define EPS_N   1e-10f
#define BETA    3.0f
#define STDV    0.05f
#define IDXMASK 0xFFFFF800u

__device__ float4 g_srcgrad[2][NPTS];          // src-query grads
__device__ float4 g_cand[2][NPTS][NCAND];      // candidate coords {x,y,z,|p|^2}
__device__ int    g_cnt[2][NPTS][NOCT];        // per-octant candidate counts
__device__ float  g_partial[GB];

__device__ __forceinline__ void ins5key(int key, int& s0, int& s1, int& s2, int& s3, int& s4) {
    s4 = key;
    int a;
    a = min(s3, s4); s4 = max(s3, s4); s3 = a;
    a = min(s2, s3); s3 = max(s2, s3); s2 = a;
    a = min(s1, s2); s2 = max(s1, s2); s1 = a;
    a = min(s0, s1); s1 = max(s0, s1); s0 = a;
}

__device__ __forceinline__ unsigned long long packf2(float lo, float hi) {
    unsigned long long r;
    asm("mov.b64 %0, {%1, %2};" : "=l"(r) : "f"(lo), "f"(hi));
    return r;
}

// ================= Kernel A: full scans (parents + src queries) =============
__global__ __launch_bounds__(TA)
void kernelA(const float* __restrict__ src,
             const float* __restrict__ tgt,
             const float* __restrict__ noise)
{
    __shared__ float4 sC[NPTS];               // 32 KB pair-SoA cloud
    __shared__ int    sKeys[NSEG-1][KNN][32]; // 9.4 KB merge buffer
    __shared__ float  sR2[32];                // per-task collection radius^2

    const int tid  = threadIdx.x;
    const int lane = tid & 31;
    const int seg  = tid >> 5;                // 0..15 scan segment
    const int b    = blockIdx.x;
    const int cat  = b >> 6;                  // 0: tgtP/tgt 1: tgtP/src 2: srcQ/tgt 3: srcQ/src
    const int grp  = b & 63;
    const bool isParent = (cat < 2);
    const float* __restrict__ cld = (cat & 1) ? src : tgt;

    for (int i = tid; i < NPTS; i += TA) {
        float x = cld[3*i], y = cld[3*i+1], z = cld[3*i+2];
        float w = fmaf(x, x, fmaf(y, y, z * z));
        int pj = i >> 1, h = i & 1;
        float* base = (float*)&sC[2 * pj];
        base[0 + h] = x; base[2 + h] = y; base[4 + h] = z; base[6 + h] = w;
    }
    __syncthreads();

    const int task = grp * 32 + lane;         // 0..2047
    const float* __restrict__ qp = isParent ? tgt : src;
    const float qx = qp[3*task], qy = qp[3*task+1], qz = qp[3*task+2];
    const float qx2 = -2.0f * qx, qy2 = -2.0f * qy, qz2 = -2.0f * qz;
    const float q2  = fmaf(qx, qx, fmaf(qy, qy, qz * qz));
    const unsigned long long qxp = packf2(qx2, qx2);
    const unsigned long long qyp = packf2(qy2, qy2);
    const unsigned long long qzp = packf2(qz2, qz2);

    int s0 = 0x7F000000, s1 = 0x7F000001, s2 = 0x7F000002,
        s3 = 0x7F000003, s4 = 0x7F000004;
    float thr = __int_as_float(s4) - q2;

    // Pass 1: broadcast scan of this warp's segment (uniform addr, no conflicts).
    const ulonglong2* pc = reinterpret_cast<const ulonglong2*>(sC) + seg * (SPAIRS * 2);
    const int joff = seg * (SPAIRS * 2);      // point-index offset

    if (isParent) {
        // value-only inserts (no index packing; clamp keeps float-bit ordering)
#pragma unroll 4
        for (int k = 0; k < SPAIRS / 2; ++k) {
            ulonglong2 A0 = pc[4 * k];
            ulonglong2 B0 = pc[4 * k + 1];
            ulonglong2 A1 = pc[4 * k + 2];
            ulonglong2 B1 = pc[4 * k + 3];
            unsigned long long ra, rb;
            asm("fma.rn.f32x2 %0, %1, %2, %3;" : "=l"(ra) : "l"(B0.x), "l"(qzp), "l"(B0.y));
            asm("fma.rn.f32x2 %0, %1, %2, %3;" : "=l"(rb) : "l"(B1.x), "l"(qzp), "l"(B1.y));
            asm("fma.rn.f32x2 %0, %1, %2, %3;" : "=l"(ra) : "l"(A0.y), "l"(qyp), "l"(ra));
            asm("fma.rn.f32x2 %0, %1, %2, %3;" : "=l"(rb) : "l"(A1.y), "l"(qyp), "l"(rb));
            asm("fma.rn.f32x2 %0, %1, %2, %3;" : "=l"(ra) : "l"(A0.x), "l"(qxp), "l"(ra));
            asm("fma.rn.f32x2 %0, %1, %2, %3;" : "=l"(rb) : "l"(A1.x), "l"(qxp), "l"(rb));
            float r0, r1, r2, r3;
            asm("mov.b64 {%0, %1}, %2;" : "=f"(r0), "=f"(r1) : "l"(ra));
            asm("mov.b64 {%0, %1}, %2;" : "=f"(r2), "=f"(r3) : "l"(rb));

            if (fminf(fminf(r0, r1), fminf(r2, r3)) < thr) {
                if (r0 < thr) {
                    ins5key(__float_as_int(fmaxf(r0 + q2, 0.0f)), s0, s1, s2, s3, s4);
                    thr = __int_as_float(s4) - q2;
                }
                if (r1 < thr) {
                    ins5key(__float_as_int(fmaxf(r1 + q2, 0.0f)), s0, s1, s2, s3, s4);
                    thr = __int_as_float(s4) - q2;
                }
                if (r2 < thr) {
                    ins5key(__float_as_int(fmaxf(r2 + q2, 0.0f)), s0, s1, s2, s3, s4);
                    thr = __int_as_float(s4) - q2;
                }
                if (r3 < thr) {
                    ins5key(__float_as_int(fmaxf(r3 + q2, 0.0f)), s0, s1, s2, s3, s4);
                    thr = __int_as_float(s4) - q2;
                }
            }
        }
    } else {
        // keyed inserts (indices needed for exact epilogue)
#pragma unroll 4
        for (int k = 0; k < SPAIRS / 2; ++k) {
            ulonglong2 A0 = pc[4 * k];
            ulonglong2 B0 = pc[4 * k + 1];
            ulonglong2 A1 = pc[4 * k + 2];
            ulonglong2 B1 = pc[4 * k + 3];
            unsigned long long ra, rb;
            asm("fma.rn.f32x2 %0, %1, %2, %3;" : "=l"(ra) : "l"(B0.x), "l"(qzp), "l"(B0.y));
            asm("fma.rn.f32x2 %0, %1, %2, %3;" : "=l"(rb) : "l"(B1.x), "l"(qzp), "l"(B1.y));
            asm("fma.rn.f32x2 %0, %1, %2, %3;" : "=l"(ra) : "l"(A0.y), "l"(qyp), "l"(ra));
            asm("fma.rn.f32x2 %0, %1, %2, %3;" : "=l"(rb) : "l"(A1.y), "l"(qyp), "l"(rb));
            asm("fma.rn.f32x2 %0, %1, %2, %3;" : "=l"(ra) : "l"(A0.x), "l"(qxp), "l"(ra));
            asm("fma.rn.f32x2 %0, %1, %2, %3;" : "=l"(rb) : "l"(A1.x), "l"(qxp), "l"(rb));
            float r0, r1, r2, r3;
            asm("mov.b64 {%0, %1}, %2;" : "=f"(r0), "=f"(r1) : "l"(ra));
            asm("mov.b64 {%0, %1}, %2;" : "=f"(r2), "=f"(r3) : "l"(rb));

            if (fminf(fminf(r0, r1), fminf(r2, r3)) < thr) {
                int jbase = joff + (k << 2);
                if (r0 < thr) {
                    float d2 = r0 + q2;
                    ins5key((int)((__float_as_uint(d2) & IDXMASK) | (unsigned)jbase), s0, s1, s2, s3, s4);
                    thr = __int_as_float(s4) - q2;
                }
                if (r1 < thr) {
                    float d2 = r1 + q2;
                    ins5key((int)((__float_as_uint(d2) & IDXMASK) | (unsigned)(jbase + 1)), s0, s1, s2, s3, s4);
                    thr = __int_as_float(s4) - q2;
                }
                if (r2 < thr) {
                    float d2 = r2 + q2;
                    ins5key((int)((__float_as_uint(d2) & IDXMASK) | (unsigned)(jbase + 2)), s0, s1, s2, s3, s4);
                    thr = __int_as_float(s4) - q2;
                }
                if (r3 < thr) {
                    float d2 = r3 + q2;
                    ins5key((int)((__float_as_uint(d2) & IDXMASK) | (unsigned)(jbase + 3)), s0, s1, s2, s3, s4);
                    thr = __int_as_float(s4) - q2;
                }
            }
        }
    }

    if (seg) {
        sKeys[seg - 1][0][lane] = s0;
        sKeys[seg - 1][1][lane] = s1;
        sKeys[seg - 1][2][lane] = s2;
        sKeys[seg - 1][3][lane] = s3;
        sKeys[seg - 1][4][lane] = s4;
    }
    __syncthreads();

    if (seg == 0) {
#pragma unroll
        for (int w = 0; w < NSEG - 1; ++w) {
#pragma unroll
            for (int r = 0; r < KNN; ++r) {
                int o = sKeys[w][r][lane];
                if (o < s4) ins5key(o, s0, s1, s2, s3, s4);
            }
        }
        if (isParent) {
            float dl2 = 0.f;
#pragma unroll
            for (int u = 0; u < UPR; ++u) {
                int nb = 3 * (task * UPR + u);
                float nx = noise[nb], ny = noise[nb+1], nz = noise[nb+2];
                dl2 = fmaxf(dl2, fmaf(nx, nx, fmaf(ny, ny, nz * nz)));
            }
            float dl = STDV * sqrtf(dl2);
            float d5 = sqrtf(__int_as_float(s4));   // exact, non-negative by clamp
            float R  = fmaf(d5, 1.002f, 2.0f * dl + 1e-4f);
            sR2[lane] = R * R;
        } else {
            float aw = 0.f, gx = 0.f, gy = 0.f, gz = 0.f;
            int keys[KNN] = {s0, s1, s2, s3, s4};
#pragma unroll
            for (int kk = 0; kk < KNN; ++kk) {
                int idx = keys[kk] & 2047;
                int pj = idx >> 1, h = idx & 1;
                const float* base = (const float*)&sC[2 * pj];
                float dx = qx - base[0 + h], dy = qy - base[2 + h], dz = qz - base[4 + h];
                float d2 = fmaf(dx, dx, fmaf(dy, dy, dz * dz));
                float w  = 1.0f / (d2 + EPS_D);
                aw += w;
                gx = fmaf(dx, w, gx);
                gy = fmaf(dy, w, gy);
                gz = fmaf(dz, w, gz);
            }
            float inv = 1.0f / aw;
            g_srcgrad[cat - 2][task] = make_float4(gx * inv, gy * inv, gz * inv, 0.f);
        }
    }
    __syncthreads();

    if (isParent && seg < NOCT) {
        const int oct = seg;
        const float thrC = sR2[lane] - q2;
        int c = 0;
        float4* out = &g_cand[cat][task][oct * SEGCAP];
#pragma unroll 2
        for (int k = 0; k < OPAIRS; ++k) {
            int pj = oct * OPAIRS + k;
            float4 a  = sC[2 * pj];
            float4 bb = sC[2 * pj + 1];
            float r0 = fmaf(a.x, qx2, fmaf(a.z, qy2, fmaf(bb.x, qz2, bb.z)));
            float r1 = fmaf(a.y, qx2, fmaf(a.w, qy2, fmaf(bb.y, qz2, bb.w)));
            if (r0 <= thrC) { if (c < SEGCAP) out[c] = make_float4(a.x, a.z, bb.x, bb.z); c++; }
            if (r1 <= thrC) { if (c < SEGCAP) out[c] = make_float4(a.y, a.w, bb.y, bb.w); c++; }
        }
        g_cnt[cat][task][oct] = c;   // c > SEGCAP signals overflow
    }
}

// ================= Kernel B: jitter queries over candidates + combine =======
// (verbatim R15 version — cold thresholds, no fused reduce)
__global__ __launch_bounds__(TB)
void kernelB(const float* __restrict__ src,
             const float* __restrict__ tgt,
             const float* __restrict__ noise)
{
    __shared__ float sh[TB / 32];
    const int tid  = threadIdx.x;
    const int gidx = blockIdx.x * TB + tid;
    const int qv   = gidx >> 1;
    const int cat  = gidx & 1;       // 0 = vs tgt, 1 = vs src

    float4 g;
    if (qv < NJIT) {
        const int m = qv / UPR;
        float qx = fmaf(noise[3*qv + 0], STDV, tgt[3*m + 0]);
        float qy = fmaf(noise[3*qv + 1], STDV, tgt[3*m + 1]);
        float qz = fmaf(noise[3*qv + 2], STDV, tgt[3*m + 2]);
        const float qx2 = -2.0f * qx, qy2 = -2.0f * qy, qz2 = -2.0f * qz;
        const float q2  = fmaf(qx, qx, fmaf(qy, qy, qz * qz));

        int s0 = 0x7F000000, s1 = 0x7F000001, s2 = 0x7F000002,
            s3 = 0x7F000003, s4 = 0x7F000004;
        float thrD = __int_as_float(s4);

        const float4* __restrict__ cl = g_cand[cat][m];
        const int4* cn4 = reinterpret_cast<const int4*>(g_cnt[cat][m]);
        int4 cA = cn4[0], cB = cn4[1];
        int cnts[NOCT] = {cA.x, cA.y, cA.z, cA.w, cB.x, cB.y, cB.z, cB.w};
        bool ovf = false;
#pragma unroll
        for (int sgi = 0; sgi < NOCT; ++sgi) ovf |= (cnts[sgi] > SEGCAP);

        if (!ovf) {
#pragma unroll
            for (int sgi = 0; sgi < NOCT; ++sgi) {
                int n = cnts[sgi];
                const float4* p = cl + sgi * SEGCAP;
                for (int i = 0; i < n; ++i) {
                    float4 c = p[i];
                    float r  = fmaf(c.x, qx2, fmaf(c.y, qy2, fmaf(c.z, qz2, c.w)));
                    float d2 = r + q2;
                    if (d2 < thrD) {
                        ins5key((int)((__float_as_uint(d2) & IDXMASK) | (unsigned)(sgi * SEGCAP + i)),
                                s0, s1, s2, s3, s4);
                        thrD = __int_as_float(s4);
                    }
                }
            }
            float aw = 0.f, gx = 0.f, gy = 0.f, gz = 0.f;
            int keys[KNN] = {s0, s1, s2, s3, s4};
#pragma unroll
            for (int kk = 0; kk < KNN; ++kk) {
                float4 c = cl[keys[kk] & 2047];
                float dx = qx - c.x, dy = qy - c.y, dz = qz - c.z;
                float d2 = fmaf(dx, dx, fmaf(dy, dy, dz * dz));
                float w  = 1.0f / (d2 + EPS_D);
                aw += w;
                gx = fmaf(dx, w, gx);
                gy = fmaf(dy, w, gy);
                gz = fmaf(dz, w, gz);
            }
            float inv = 1.0f / aw;
            g = make_float4(gx * inv, gy * inv, gz * inv, 0.f);
        } else {
            // overflow fallback: exact full scan from global (rare)
            const float* fp = cat ? src : tgt;
            for (int idx = 0; idx < NPTS; ++idx) {
                float x = fp[3*idx], y = fp[3*idx+1], z = fp[3*idx+2];
                float w = fmaf(x, x, fmaf(y, y, z * z));
                float r = fmaf(x, qx2, fmaf(y, qy2, fmaf(z, qz2, w)));
                float d2 = r + q2;
                if (d2 < thrD) {
                    ins5key((int)((__float_as_uint(d2) & IDXMASK) | (unsigned)idx),
                            s0, s1, s2, s3, s4);
                    thrD = __int_as_float(s4);
                }
            }
            float aw = 0.f, gx = 0.f, gy = 0.f, gz = 0.f;
            int keys[KNN] = {s0, s1, s2, s3, s4};
#pragma unroll
            for (int kk = 0; kk < KNN; ++kk) {
                int idx = keys[kk] & 2047;
                float dx = qx - fp[3*idx], dy = qy - fp[3*idx+1], dz = qz - fp[3*idx+2];
                float d2 = fmaf(dx, dx, fmaf(dy, dy, dz * dz));
                float w  = 1.0f / (d2 + EPS_D);
                aw += w;
                gx = fmaf(dx, w, gx);
                gy = fmaf(dy, w, gy);
                gz = fmaf(dz, w, gz);
            }
            float inv = 1.0f / aw;
            g = make_float4(gx * inv, gy * inv, gz * inv, 0.f);
        }
    } else {
        g = g_srcgrad[cat][qv - NJIT];
    }

    // partner-lane combine: cat0 holds gT, receives gS from cat1 lane.
    float ox = __shfl_xor_sync(0xFFFFFFFFu, g.x, 1);
    float oy = __shfl_xor_sync(0xFFFFFFFFu, g.y, 1);
    float oz = __shfl_xor_sync(0xFFFFFFFFu, g.z, 1);

    float v = 0.f;
    if (cat == 0) {
        float axT = g.x + EPS_N, ayT = g.y + EPS_N, azT = g.z + EPS_N;
        float axS = ox  + EPS_N, ayS = oy  + EPS_N, azS = oz  + EPS_N;
        float uT = sqrtf(fmaf(axT, axT, fmaf(ayT, ayT, azT * azT)));
        float uS = sqrtf(fmaf(axS, axS, fmaf(ayS, ayS, azS * azS)));
        float e1 = fabsf(uT - uS);
        float e2 = fabsf(ox - g.x) + fabsf(oy - g.y) + fabsf(oz - g.z);
        float tt = e1 + e2;
        v = tt * __expf(-BETA * tt);
    }

#pragma unroll
    for (int o = 16; o > 0; o >>= 1) v += __shfl_down_sync(0xFFFFFFFFu, v, o);
    if ((tid & 31) == 0) sh[tid >> 5] = v;
    __syncthreads();
    if (tid == 0) {
        float s = 0.f;
#pragma unroll
        for (int w = 0; w < TB / 32; ++w) s += sh[w];
        g_partial[blockIdx.x] = s;
    }
}

__global__ void final_reduce(float* __restrict__ out)
{
    __shared__ float sh[8];
    int tid = threadIdx.x;   // 256
    float v = 0.f;
    for (int i = tid; i < GB; i += 256) v += g_partial[i];
#pragma unroll
    for (int o = 16; o > 0; o >>= 1) v += __shfl_down_sync(0xFFFFFFFFu, v, o);
    if ((tid & 31) == 0) sh[tid >> 5] = v;
    __syncthreads();
    if (tid == 0) {
        float s = 0.f;
#pragma unroll
        for (int w = 0; w < 8; ++w) s += sh[w];
        out[0] = s * (1.0f / (float)QTOT);
    }
}

extern "C" void kernel_launch(void* const* d_in, const int* in_sizes, int n_in,
                              void* d_out, int out_size)
{
    const float* src   = (const float*)d_in[0];
    const float* tgt   = (const float*)d_in[1];
    const float* noise = (const float*)d_in[2];
    (void)in_sizes; (void)n_in; (void)out_size;

    kernelA<<<GA, TA>>>(src, tgt, noise);
    kernelB<<<GB, TB>>>(src, tgt, noise);
    final_reduce<<<1, 256>>>((float*)d_out);
}